// round 2
// baseline (speedup 1.0000x reference)
#include <cuda_runtime.h>
#include <math.h>

#define T_TOK 8192
#define DM    512
#define DFF   2048
#define NE    64
#define CAP   320   // ceil(8192*2/64 * 1.25)

// ---------------- scratch (device globals: no allocations allowed) ----------
__device__ int   g_flat_e[T_TOK * 2];
__device__ int   g_entry_slot[T_TOK * 2];
__device__ int   g_slot_tok[NE * CAP];
__device__ float g_H[(size_t)NE * CAP * DFF];   // 168 MB
__device__ float g_Y[(size_t)NE * CAP * DM];    // 42 MB

// ---------------- 1) routing: warp per token, hashes 0 and 1 ----------------
__global__ void route_kernel(const float* __restrict__ x,
                             const float* __restrict__ Wh) {
    int gw   = (blockIdx.x * blockDim.x + threadIdx.x) >> 5;
    int lane = threadIdx.x & 31;
    if (gw >= T_TOK) return;
    const float* xr = x + (size_t)gw * DM;
    float d0 = 0.f, d1 = 0.f;
    #pragma unroll
    for (int j = lane; j < DM; j += 32) {
        float v = xr[j];
        d0 = fmaf(v, Wh[j],      d0);
        d1 = fmaf(v, Wh[DM + j], d1);
    }
    #pragma unroll
    for (int o = 16; o > 0; o >>= 1) {
        d0 += __shfl_down_sync(0xffffffffu, d0, o);
        d1 += __shfl_down_sync(0xffffffffu, d1, o);
    }
    if (lane == 0) {
        // bucket = mod(int(floor(score*8)) + LAYER_ID(0), 64); &63 == python mod
        g_flat_e[2 * gw]     = ((int)floorf(d0 * 8.0f)) & 63;
        g_flat_e[2 * gw + 1] = ((int)floorf(d1 * 8.0f)) & 63;
    }
}

// ---------------- 2) order-preserving rank, single block ---------------------
__global__ void rank_kernel() {
    __shared__ int counts[NE];
    __shared__ int whist[32][NE];
    __shared__ int wpref[32][NE];
    __shared__ int ttot[NE];
    int tid  = threadIdx.x;
    int w    = tid >> 5;
    int lane = tid & 31;
    unsigned lmask = (1u << lane) - 1u;

    if (tid < NE) counts[tid] = 0;
    for (int j = tid; j < NE * CAP; j += 1024) g_slot_tok[j] = -1;
    __syncthreads();

    for (int tile = 0; tile < (T_TOK * 2) / 1024; tile++) {
        for (int j = tid; j < 32 * NE; j += 1024) (&whist[0][0])[j] = 0;
        __syncthreads();

        int i = tile * 1024 + tid;
        int e = g_flat_e[i];
        unsigned m  = __match_any_sync(0xffffffffu, e);
        int prior   = __popc(m & lmask);
        if ((m & lmask) == 0) whist[w][e] = __popc(m);   // group leader
        __syncthreads();

        if (tid < NE) {                                   // scan over 32 warps
            int s = 0;
            #pragma unroll
            for (int ww = 0; ww < 32; ww++) { wpref[ww][tid] = s; s += whist[ww][tid]; }
            ttot[tid] = s;
        }
        __syncthreads();

        int pos = counts[e] + wpref[w][e] + prior;
        if (pos < CAP) {
            g_entry_slot[i]            = e * CAP + pos;
            g_slot_tok[e * CAP + pos]  = i >> 1;          // token index
        } else {
            g_entry_slot[i] = -1;
        }
        __syncthreads();
        if (tid < NE) counts[tid] += ttot[tid];
        __syncthreads();
    }
}

// ---------------- 3) GEMM1: H = gelu(gather(x) @ W1 + b1) --------------------
// per expert: M=CAP(320) x K=512 x N=2048.  BM=64 BN=128 BK=16, 256 thr, 8x4.
__global__ __launch_bounds__(256) void gemm1_kernel(
        const float* __restrict__ x,
        const float* __restrict__ W1,
        const float* __restrict__ b1) {
    __shared__ float As[16][68];     // [k][m], padded stride 68 (16B aligned)
    __shared__ float Bs[16][128];    // [k][n]
    __shared__ int   stok[64];

    int e  = blockIdx.z;
    int m0 = blockIdx.y * 64;
    int n0 = blockIdx.x * 128;
    int tid = threadIdx.x;
    if (tid < 64) stok[tid] = g_slot_tok[e * CAP + m0 + tid];
    __syncthreads();

    const float* Wb = W1 + (size_t)e * DM * DFF;
    float acc[8][4];
    #pragma unroll
    for (int i = 0; i < 8; i++)
        #pragma unroll
        for (int j = 0; j < 4; j++) acc[i][j] = 0.f;

    int ty = tid >> 5;          // row group 0..7  (rows ty*8..ty*8+7)
    int tx = tid & 31;          // col group       (cols tx*4..tx*4+3)
    int lm = tid >> 2;          // A-load row 0..63
    int lk = (tid & 3) * 4;     // A-load k offset

    for (int k0 = 0; k0 < DM; k0 += 16) {
        {   // gathered A tile
            int tok = stok[lm];
            float4 v = make_float4(0.f, 0.f, 0.f, 0.f);
            if (tok >= 0)
                v = *(const float4*)(x + (size_t)tok * DM + k0 + lk);
            As[lk + 0][lm] = v.x; As[lk + 1][lm] = v.y;
            As[lk + 2][lm] = v.z; As[lk + 3][lm] = v.w;
        }
        #pragma unroll
        for (int r = 0; r < 2; r++) {       // B tile: 2 x float4 per thread
            int f4 = tid + r * 256;
            int kk = f4 >> 5;
            int nn = (f4 & 31) * 4;
            *(float4*)&Bs[kk][nn] =
                *(const float4*)(Wb + (size_t)(k0 + kk) * DFF + n0 + nn);
        }
        __syncthreads();
        #pragma unroll
        for (int k = 0; k < 16; k++) {
            float4 a0 = *(const float4*)&As[k][ty * 8];
            float4 a1 = *(const float4*)&As[k][ty * 8 + 4];
            float4 b  = *(const float4*)&Bs[k][tx * 4];
            float av[8] = {a0.x, a0.y, a0.z, a0.w, a1.x, a1.y, a1.z, a1.w};
            float bv[4] = {b.x, b.y, b.z, b.w};
            #pragma unroll
            for (int i = 0; i < 8; i++)
                #pragma unroll
                for (int j = 0; j < 4; j++)
                    acc[i][j] = fmaf(av[i], bv[j], acc[i][j]);
        }
        __syncthreads();
    }

    float* Hb = g_H + (size_t)e * CAP * DFF;
    int nb = n0 + tx * 4;
    float4 bias = *(const float4*)(b1 + (size_t)e * DFF + nb);
    #pragma unroll
    for (int i = 0; i < 8; i++) {
        int m = m0 + ty * 8 + i;
        float4 o;
        float h;
        h = acc[i][0] + bias.x; o.x = 0.5f * h * (1.0f + erff(h * 0.70710678118654752f));
        h = acc[i][1] + bias.y; o.y = 0.5f * h * (1.0f + erff(h * 0.70710678118654752f));
        h = acc[i][2] + bias.z; o.z = 0.5f * h * (1.0f + erff(h * 0.70710678118654752f));
        h = acc[i][3] + bias.w; o.w = 0.5f * h * (1.0f + erff(h * 0.70710678118654752f));
        *(float4*)(Hb + (size_t)m * DFF + nb) = o;
    }
}

// ---------------- 4) GEMM2: Y = H @ W2 + b2 ----------------------------------
// per expert: M=320 x K=2048 x N=512. Same tiling.
__global__ __launch_bounds__(256) void gemm2_kernel(
        const float* __restrict__ W2,
        const float* __restrict__ b2) {
    __shared__ float As[16][68];
    __shared__ float Bs[16][128];

    int e  = blockIdx.z;
    int m0 = blockIdx.y * 64;
    int n0 = blockIdx.x * 128;
    int tid = threadIdx.x;

    const float* Ab = g_H + (size_t)e * CAP * DFF;
    const float* Wb = W2 + (size_t)e * DFF * DM;
    float acc[8][4];
    #pragma unroll
    for (int i = 0; i < 8; i++)
        #pragma unroll
        for (int j = 0; j < 4; j++) acc[i][j] = 0.f;

    int ty = tid >> 5;
    int tx = tid & 31;
    int lm = tid >> 2;
    int lk = (tid & 3) * 4;

    for (int k0 = 0; k0 < DFF; k0 += 16) {
        {
            float4 v = *(const float4*)(Ab + (size_t)(m0 + lm) * DFF + k0 + lk);
            As[lk + 0][lm] = v.x; As[lk + 1][lm] = v.y;
            As[lk + 2][lm] = v.z; As[lk + 3][lm] = v.w;
        }
        #pragma unroll
        for (int r = 0; r < 2; r++) {
            int f4 = tid + r * 256;
            int kk = f4 >> 5;
            int nn = (f4 & 31) * 4;
            *(float4*)&Bs[kk][nn] =
                *(const float4*)(Wb + (size_t)(k0 + kk) * DM + n0 + nn);
        }
        __syncthreads();
        #pragma unroll
        for (int k = 0; k < 16; k++) {
            float4 a0 = *(const float4*)&As[k][ty * 8];
            float4 a1 = *(const float4*)&As[k][ty * 8 + 4];
            float4 b  = *(const float4*)&Bs[k][tx * 4];
            float av[8] = {a0.x, a0.y, a0.z, a0.w, a1.x, a1.y, a1.z, a1.w};
            float bv[4] = {b.x, b.y, b.z, b.w};
            #pragma unroll
            for (int i = 0; i < 8; i++)
                #pragma unroll
                for (int j = 0; j < 4; j++)
                    acc[i][j] = fmaf(av[i], bv[j], acc[i][j]);
        }
        __syncthreads();
    }

    float* Yb = g_Y + (size_t)e * CAP * DM;
    int nb = n0 + tx * 4;
    float4 bias = *(const float4*)(b2 + (size_t)e * DM + nb);
    #pragma unroll
    for (int i = 0; i < 8; i++) {
        int m = m0 + ty * 8 + i;
        float4 o;
        o.x = acc[i][0] + bias.x;
        o.y = acc[i][1] + bias.y;
        o.z = acc[i][2] + bias.z;
        o.w = acc[i][3] + bias.w;
        *(float4*)(Yb + (size_t)m * DM + nb) = o;
    }
}

// ---------------- 5) output gather + mean over the 2 routes ------------------
__global__ void out_kernel(float* __restrict__ out) {
    int idx = blockIdx.x * blockDim.x + threadIdx.x;     // over T*DM/4
    if (idx >= T_TOK * DM / 4) return;
    int t  = idx / (DM / 4);
    int d4 = (idx % (DM / 4)) * 4;
    int s0 = g_entry_slot[2 * t];
    int s1 = g_entry_slot[2 * t + 1];
    float4 r = make_float4(0.f, 0.f, 0.f, 0.f);
    if (s0 >= 0) {
        float4 v = *(const float4*)(g_Y + (size_t)s0 * DM + d4);
        r.x += v.x; r.y += v.y; r.z += v.z; r.w += v.w;
    }
    if (s1 >= 0) {
        float4 v = *(const float4*)(g_Y + (size_t)s1 * DM + d4);
        r.x += v.x; r.y += v.y; r.z += v.z; r.w += v.w;
    }
    r.x *= 0.5f; r.y *= 0.5f; r.z *= 0.5f; r.w *= 0.5f;
    *(float4*)(out + (size_t)idx * 4) = r;
}

// ---------------- launch ----------------------------------------------------
extern "C" void kernel_launch(void* const* d_in, const int* in_sizes, int n_in,
                              void* d_out, int out_size) {
    const float* x   = (const float*)d_in[0];  // [4,2048,512]
    const float* Wh  = (const float*)d_in[1];  // [4,512]
    const float* W1  = (const float*)d_in[2];  // [64,512,2048]
    const float* b1  = (const float*)d_in[3];  // [64,2048]
    const float* W2  = (const float*)d_in[4];  // [64,2048,512]
    const float* b2  = (const float*)d_in[5];  // [64,512]
    float* out = (float*)d_out;

    route_kernel<<<T_TOK / 8, 256>>>(x, Wh);
    rank_kernel<<<1, 1024>>>();
    gemm1_kernel<<<dim3(DFF / 128, CAP / 64, NE), 256>>>(x, W1, b1);
    gemm2_kernel<<<dim3(DM / 128, CAP / 64, NE), 256>>>(W2, b2);
    out_kernel<<<(T_TOK * DM / 4 + 255) / 256, 256>>>(out);
}

// round 4
// speedup vs baseline: 2.5950x; 2.5950x over previous
#include <cuda_runtime.h>
#include <math.h>
#include <stdint.h>

#define T_TOK 8192
#define DM    512
#define DFF   2048
#define NE    64
#define CAP   320
#define CAPP  384   // padded capacity (3 x 128)

// ---------------- scratch ----------------------------------------------------
__device__ int   g_flat_e[T_TOK * 2];
__device__ int   g_entry_slot[T_TOK * 2];
__device__ int   g_slot_tok[NE * CAPP];
__device__ float g_H[(size_t)NE * CAPP * DFF];
__device__ float g_Y[(size_t)NE * CAPP * DM];

// ---------------- helpers ----------------------------------------------------
__device__ __forceinline__ uint32_t smem_u32(const void* p) {
    uint32_t a;
    asm("{ .reg .u64 t; cvta.to.shared.u64 t, %1; cvt.u32.u64 %0, t; }"
        : "=r"(a) : "l"(p));
    return a;
}
__device__ __forceinline__ uint32_t cvt_tf32(float f) {
    uint32_t r; asm("cvt.rna.tf32.f32 %0, %1;" : "=r"(r) : "f"(f)); return r;
}
__device__ __forceinline__ uint4 cvt4(float4 v) {
    uint4 t;
    t.x = cvt_tf32(v.x); t.y = cvt_tf32(v.y);
    t.z = cvt_tf32(v.z); t.w = cvt_tf32(v.w);
    return t;
}
__device__ __forceinline__ void ldsm4(uint32_t* r, uint32_t addr) {
    asm volatile("ldmatrix.sync.aligned.m8n8.x4.shared.b16 {%0,%1,%2,%3}, [%4];"
                 : "=r"(r[0]), "=r"(r[1]), "=r"(r[2]), "=r"(r[3]) : "r"(addr));
}
__device__ __forceinline__ void mma8(float* d, const uint32_t* a, const uint32_t* b) {
    asm volatile("mma.sync.aligned.m16n8k8.row.col.f32.tf32.tf32.f32 "
                 "{%0,%1,%2,%3}, {%4,%5,%6,%7}, {%8,%9}, {%0,%1,%2,%3};"
                 : "+f"(d[0]), "+f"(d[1]), "+f"(d[2]), "+f"(d[3])
                 : "r"(a[0]), "r"(a[1]), "r"(a[2]), "r"(a[3]),
                   "r"(b[0]), "r"(b[1]));
}
__device__ __forceinline__ float gelu_f(float h) {
    return 0.5f * h * (1.0f + erff(h * 0.70710678118654752f));
}

// smem geometry (bytes)
#define A_STRIDE 144            // 32 k-floats + 4 pad
#define A_BUF    (128 * A_STRIDE)          // 18432
#define B_STRIDE 544            // 128 n-floats + 8 pad
#define B_BUF    (32 * B_STRIDE)           // 17408
#define SMEM_TOT (2 * A_BUF + 2 * B_BUF)   // 71680

// ---------------- 1) routing -------------------------------------------------
__global__ void route_kernel(const float* __restrict__ x,
                             const float* __restrict__ Wh) {
    int gw   = (blockIdx.x * blockDim.x + threadIdx.x) >> 5;
    int lane = threadIdx.x & 31;
    if (gw >= T_TOK) return;
    const float* xr = x + (size_t)gw * DM;
    float d0 = 0.f, d1 = 0.f;
    #pragma unroll
    for (int j = lane; j < DM; j += 32) {
        float v = xr[j];
        d0 = fmaf(v, Wh[j],      d0);
        d1 = fmaf(v, Wh[DM + j], d1);
    }
    #pragma unroll
    for (int o = 16; o > 0; o >>= 1) {
        d0 += __shfl_down_sync(0xffffffffu, d0, o);
        d1 += __shfl_down_sync(0xffffffffu, d1, o);
    }
    if (lane == 0) {
        g_flat_e[2 * gw]     = ((int)floorf(d0 * 8.0f)) & 63;
        g_flat_e[2 * gw + 1] = ((int)floorf(d1 * 8.0f)) & 63;
    }
}

// ---------------- 2) order-preserving rank -----------------------------------
__global__ void rank_kernel() {
    __shared__ int counts[NE];
    __shared__ int whist[32][NE];
    __shared__ int wpref[32][NE];
    __shared__ int ttot[NE];
    int tid  = threadIdx.x;
    int w    = tid >> 5;
    int lane = tid & 31;
    unsigned lmask = (1u << lane) - 1u;

    if (tid < NE) counts[tid] = 0;
    for (int j = tid; j < NE * CAPP; j += 1024) g_slot_tok[j] = -1;
    __syncthreads();

    for (int tile = 0; tile < (T_TOK * 2) / 1024; tile++) {
        for (int j = tid; j < 32 * NE; j += 1024) (&whist[0][0])[j] = 0;
        __syncthreads();

        int i = tile * 1024 + tid;
        int e = g_flat_e[i];
        unsigned m  = __match_any_sync(0xffffffffu, e);
        int prior   = __popc(m & lmask);
        if ((m & lmask) == 0) whist[w][e] = __popc(m);
        __syncthreads();

        if (tid < NE) {
            int s = 0;
            #pragma unroll
            for (int ww = 0; ww < 32; ww++) { wpref[ww][tid] = s; s += whist[ww][tid]; }
            ttot[tid] = s;
        }
        __syncthreads();

        int pos = counts[e] + wpref[w][e] + prior;
        if (pos < CAP) {
            g_entry_slot[i]            = e * CAPP + pos;
            g_slot_tok[e * CAPP + pos] = i >> 1;
        } else {
            g_entry_slot[i] = -1;
        }
        __syncthreads();
        if (tid < NE) counts[tid] += ttot[tid];
        __syncthreads();
    }
}

// ---------------- 3) GEMM1: H = gelu(gather(x) @ W1 + b1)  (mma.sync tf32) ---
__global__ __launch_bounds__(256, 2) void xw1_kernel(
        const float* __restrict__ x, const float* __restrict__ W1,
        const float* __restrict__ b1) {
    extern __shared__ char smem[];
    uint32_t sb = smem_u32(smem);
    int tid = threadIdx.x, lane = tid & 31, wid = tid >> 5;
    int wm = wid & 3, wn = wid >> 2;
    int g = lane >> 2, q = lane & 3;
    int n0 = blockIdx.x * 128, mt = blockIdx.y, e = blockIdx.z;

    const float* Wb = W1 + (size_t)e * DM * DFF;

    int tok[4];
    #pragma unroll
    for (int i = 0; i < 4; i++)
        tok[i] = g_slot_tok[e * CAPP + mt * 128 + (tid >> 3) + 32 * i];

    float acc[2][8][4];
    #pragma unroll
    for (int mf = 0; mf < 2; mf++)
        #pragma unroll
        for (int nf = 0; nf < 8; nf++)
            #pragma unroll
            for (int j = 0; j < 4; j++) acc[mf][nf][j] = 0.f;

    float4 regA[4], regB[4];
    int akq = (tid & 7) * 4;
    int bn4 = (tid & 31) * 4;

    auto ldg = [&](int k0) {
        #pragma unroll
        for (int i = 0; i < 4; i++) {
            int t = tok[i];
            regA[i] = (t >= 0) ? *(const float4*)(x + (size_t)t * DM + k0 + akq)
                               : make_float4(0.f, 0.f, 0.f, 0.f);
        }
        #pragma unroll
        for (int i = 0; i < 4; i++) {
            int kk = (tid >> 5) + 8 * i;
            regB[i] = *(const float4*)(Wb + (size_t)(k0 + kk) * DFF + n0 + bn4);
        }
    };
    auto sts = [&](int st) {
        char* Ab = smem + st * A_BUF;
        char* Bb = smem + 2 * A_BUF + st * B_BUF;
        #pragma unroll
        for (int i = 0; i < 4; i++)
            *(uint4*)(Ab + ((tid >> 3) + 32 * i) * A_STRIDE + akq * 4) = cvt4(regA[i]);
        #pragma unroll
        for (int i = 0; i < 4; i++)
            *(uint4*)(Bb + ((tid >> 5) + 8 * i) * B_STRIDE + bn4 * 4) = cvt4(regB[i]);
    };
    int arow = wm * 32 + (lane & 7) + ((lane >> 3) & 1) * 8;
    int agr  = (lane >> 4);
    auto compute = [&](int st) {
        uint32_t Abase = sb + st * A_BUF;
        const char* Bb = smem + 2 * A_BUF + st * B_BUF;
        #pragma unroll
        for (int ks = 0; ks < 4; ks++) {
            uint32_t af[2][4];
            #pragma unroll
            for (int mf = 0; mf < 2; mf++)
                ldsm4(af[mf], Abase + (arow + mf * 16) * A_STRIDE + (agr + 2 * ks) * 16);
            const char* Brow = Bb + (ks * 8 + q) * B_STRIDE + (wn * 64 + g) * 4;
            #pragma unroll
            for (int nf = 0; nf < 8; nf++) {
                uint32_t bb[2];
                bb[0] = *(const uint32_t*)(Brow + nf * 32);
                bb[1] = *(const uint32_t*)(Brow + 4 * B_STRIDE + nf * 32);
                mma8(acc[0][nf], af[0], bb);
                mma8(acc[1][nf], af[1], bb);
            }
        }
    };

    ldg(0); sts(0); __syncthreads();
    #pragma unroll 1
    for (int c = 0; c < 16; c++) {
        if (c + 1 < 16) ldg((c + 1) * 32);
        compute(c & 1);
        if (c + 1 < 16) { sts((c + 1) & 1); __syncthreads(); }
    }

    const float* b1e = b1 + (size_t)e * DFF + n0;
    #pragma unroll
    for (int nf = 0; nf < 8; nf++) {
        int col = wn * 64 + nf * 8 + 2 * q;
        float2 bb = *(const float2*)(b1e + col);
        #pragma unroll
        for (int mf = 0; mf < 2; mf++) {
            int r0 = mt * 128 + wm * 32 + mf * 16 + g;
            float* p0 = g_H + ((size_t)e * CAPP + r0) * DFF + n0 + col;
            float2 o0 = make_float2(gelu_f(acc[mf][nf][0] + bb.x),
                                    gelu_f(acc[mf][nf][1] + bb.y));
            *(float2*)p0 = o0;
            float2 o1 = make_float2(gelu_f(acc[mf][nf][2] + bb.x),
                                    gelu_f(acc[mf][nf][3] + bb.y));
            *(float2*)(p0 + 8 * DFF) = o1;
        }
    }
}

// ---------------- 4) GEMM2: Y = H @ W2 + b2  (mma.sync tf32) ------------------
__global__ __launch_bounds__(256, 2) void hw2_kernel(
        const float* __restrict__ W2, const float* __restrict__ b2) {
    extern __shared__ char smem[];
    uint32_t sb = smem_u32(smem);
    int tid = threadIdx.x, lane = tid & 31, wid = tid >> 5;
    int wm = wid & 3, wn = wid >> 2;
    int g = lane >> 2, q = lane & 3;
    int n0 = blockIdx.x * 128, mt = blockIdx.y, e = blockIdx.z;

    const float* Ab0 = g_H + ((size_t)e * CAPP + mt * 128) * DFF;
    const float* Wb  = W2 + (size_t)e * DFF * DM;

    float acc[2][8][4];
    #pragma unroll
    for (int mf = 0; mf < 2; mf++)
        #pragma unroll
        for (int nf = 0; nf < 8; nf++)
            #pragma unroll
            for (int j = 0; j < 4; j++) acc[mf][nf][j] = 0.f;

    float4 regA[4], regB[4];
    int akq = (tid & 7) * 4;
    int bn4 = (tid & 31) * 4;

    auto ldg = [&](int k0) {
        #pragma unroll
        for (int i = 0; i < 4; i++) {
            int m = (tid >> 3) + 32 * i;
            regA[i] = *(const float4*)(Ab0 + (size_t)m * DFF + k0 + akq);
        }
        #pragma unroll
        for (int i = 0; i < 4; i++) {
            int kk = (tid >> 5) + 8 * i;
            regB[i] = *(const float4*)(Wb + (size_t)(k0 + kk) * DM + n0 + bn4);
        }
    };
    auto sts = [&](int st) {
        char* Ab = smem + st * A_BUF;
        char* Bb = smem + 2 * A_BUF + st * B_BUF;
        #pragma unroll
        for (int i = 0; i < 4; i++)
            *(uint4*)(Ab + ((tid >> 3) + 32 * i) * A_STRIDE + akq * 4) = cvt4(regA[i]);
        #pragma unroll
        for (int i = 0; i < 4; i++)
            *(uint4*)(Bb + ((tid >> 5) + 8 * i) * B_STRIDE + bn4 * 4) = cvt4(regB[i]);
    };
    int arow = wm * 32 + (lane & 7) + ((lane >> 3) & 1) * 8;
    int agr  = (lane >> 4);
    auto compute = [&](int st) {
        uint32_t Abase = sb + st * A_BUF;
        const char* Bb = smem + 2 * A_BUF + st * B_BUF;
        #pragma unroll
        for (int ks = 0; ks < 4; ks++) {
            uint32_t af[2][4];
            #pragma unroll
            for (int mf = 0; mf < 2; mf++)
                ldsm4(af[mf], Abase + (arow + mf * 16) * A_STRIDE + (agr + 2 * ks) * 16);
            const char* Brow = Bb + (ks * 8 + q) * B_STRIDE + (wn * 64 + g) * 4;
            #pragma unroll
            for (int nf = 0; nf < 8; nf++) {
                uint32_t bb[2];
                bb[0] = *(const uint32_t*)(Brow + nf * 32);
                bb[1] = *(const uint32_t*)(Brow + 4 * B_STRIDE + nf * 32);
                mma8(acc[0][nf], af[0], bb);
                mma8(acc[1][nf], af[1], bb);
            }
        }
    };

    ldg(0); sts(0); __syncthreads();
    #pragma unroll 1
    for (int c = 0; c < 64; c++) {
        if (c + 1 < 64) ldg((c + 1) * 32);
        compute(c & 1);
        if (c + 1 < 64) { sts((c + 1) & 1); __syncthreads(); }
    }

    const float* b2e = b2 + (size_t)e * DM + n0;
    #pragma unroll
    for (int nf = 0; nf < 8; nf++) {
        int col = wn * 64 + nf * 8 + 2 * q;
        float2 bb = *(const float2*)(b2e + col);
        #pragma unroll
        for (int mf = 0; mf < 2; mf++) {
            int r0 = mt * 128 + wm * 32 + mf * 16 + g;
            float* p0 = g_Y + ((size_t)e * CAPP + r0) * DM + n0 + col;
            float2 o0 = make_float2(acc[mf][nf][0] + bb.x, acc[mf][nf][1] + bb.y);
            *(float2*)p0 = o0;
            float2 o1 = make_float2(acc[mf][nf][2] + bb.x, acc[mf][nf][3] + bb.y);
            *(float2*)(p0 + 8 * DM) = o1;
        }
    }
}

// ---------------- 5) output gather + mean ------------------------------------
__global__ void out_kernel(float* __restrict__ out) {
    int idx = blockIdx.x * blockDim.x + threadIdx.x;
    if (idx >= T_TOK * DM / 4) return;
    int t  = idx / (DM / 4);
    int d4 = (idx % (DM / 4)) * 4;
    int s0 = g_entry_slot[2 * t];
    int s1 = g_entry_slot[2 * t + 1];
    float4 r = make_float4(0.f, 0.f, 0.f, 0.f);
    if (s0 >= 0) {
        float4 v = *(const float4*)(g_Y + (size_t)s0 * DM + d4);
        r.x += v.x; r.y += v.y; r.z += v.z; r.w += v.w;
    }
    if (s1 >= 0) {
        float4 v = *(const float4*)(g_Y + (size_t)s1 * DM + d4);
        r.x += v.x; r.y += v.y; r.z += v.z; r.w += v.w;
    }
    r.x *= 0.5f; r.y *= 0.5f; r.z *= 0.5f; r.w *= 0.5f;
    *(float4*)(out + (size_t)idx * 4) = r;
}

// ---------------- launch -----------------------------------------------------
extern "C" void kernel_launch(void* const* d_in, const int* in_sizes, int n_in,
                              void* d_out, int out_size) {
    const float* x   = (const float*)d_in[0];
    const float* Wh  = (const float*)d_in[1];
    const float* W1  = (const float*)d_in[2];
    const float* b1  = (const float*)d_in[3];
    const float* W2  = (const float*)d_in[4];
    const float* b2  = (const float*)d_in[5];
    float* out = (float*)d_out;

    cudaFuncSetAttribute(xw1_kernel, cudaFuncAttributeMaxDynamicSharedMemorySize, SMEM_TOT);
    cudaFuncSetAttribute(hw2_kernel, cudaFuncAttributeMaxDynamicSharedMemorySize, SMEM_TOT);

    route_kernel<<<T_TOK / 8, 256>>>(x, Wh);
    rank_kernel<<<1, 1024>>>();
    xw1_kernel<<<dim3(DFF / 128, CAPP / 128, NE), 256, SMEM_TOT>>>(x, W1, b1);
    hw2_kernel<<<dim3(DM / 128, CAPP / 128, NE), 256, SMEM_TOT>>>(W2, b2);
    out_kernel<<<(T_TOK * DM / 4 + 255) / 256, 256>>>(out);
}

// round 7
// speedup vs baseline: 3.4762x; 1.3396x over previous
#include <cuda_runtime.h>
#include <math.h>
#include <stdint.h>

#define T_TOK 8192
#define DM    512
#define DFF   2048
#define NE    64
#define CAP   320
#define CAPP  384   // padded capacity (3 x 128)

// ---------------- scratch ----------------------------------------------------
__device__ int   g_flat_e[T_TOK * 2];
__device__ int   g_entry_slot[T_TOK * 2];
__device__ int   g_slot_tok[NE * CAPP];
__device__ float g_H[(size_t)NE * CAPP * DFF];
__device__ float g_Y[(size_t)NE * CAPP * DM];

// ---------------- helpers ----------------------------------------------------
__device__ __forceinline__ uint32_t smem_u32(const void* p) {
    uint32_t a;
    asm("{ .reg .u64 t; cvta.to.shared.u64 t, %1; cvt.u32.u64 %0, t; }"
        : "=r"(a) : "l"(p));
    return a;
}
__device__ __forceinline__ uint32_t cvt_tf32(float f) {
    uint32_t r; asm("cvt.rna.tf32.f32 %0, %1;" : "=r"(r) : "f"(f)); return r;
}
__device__ __forceinline__ uint4 cvt4(float4 v) {
    uint4 t;
    t.x = cvt_tf32(v.x); t.y = cvt_tf32(v.y);
    t.z = cvt_tf32(v.z); t.w = cvt_tf32(v.w);
    return t;
}
__device__ __forceinline__ void ldsm4(uint32_t* r, uint32_t addr) {
    asm volatile("ldmatrix.sync.aligned.m8n8.x4.shared.b16 {%0,%1,%2,%3}, [%4];"
                 : "=r"(r[0]), "=r"(r[1]), "=r"(r[2]), "=r"(r[3]) : "r"(addr));
}
__device__ __forceinline__ void lds128(uint32_t* r, uint32_t addr) {
    asm volatile("ld.shared.v4.b32 {%0,%1,%2,%3}, [%4];"
                 : "=r"(r[0]), "=r"(r[1]), "=r"(r[2]), "=r"(r[3]) : "r"(addr));
}
__device__ __forceinline__ void mma8(float* d, const uint32_t* a, const uint32_t* b) {
    asm volatile("mma.sync.aligned.m16n8k8.row.col.f32.tf32.tf32.f32 "
                 "{%0,%1,%2,%3}, {%4,%5,%6,%7}, {%8,%9}, {%0,%1,%2,%3};"
                 : "+f"(d[0]), "+f"(d[1]), "+f"(d[2]), "+f"(d[3])
                 : "r"(a[0]), "r"(a[1]), "r"(a[2]), "r"(a[3]),
                   "r"(b[0]), "r"(b[1]));
}
__device__ __forceinline__ float gelu_f(float h) {
    return 0.5f * h * (1.0f + erff(h * 0.70710678118654752f));
}

// smem geometry (bytes)
#define A_STRIDE 144                       // 32 k-floats + 4 pad
#define A_BUF    (128 * A_STRIDE)          // 18432
#define BP_BUF   16384                     // permuted B: 4096 words
#define SMEM_TOT (2 * A_BUF + 2 * BP_BUF)  // 69632

// ---------------- 1) routing -------------------------------------------------
__global__ void route_kernel(const float* __restrict__ x,
                             const float* __restrict__ Wh) {
    int gw   = (blockIdx.x * blockDim.x + threadIdx.x) >> 5;
    int lane = threadIdx.x & 31;
    if (gw >= T_TOK) return;
    const float* xr = x + (size_t)gw * DM;
    float d0 = 0.f, d1 = 0.f;
    #pragma unroll
    for (int j = lane; j < DM; j += 32) {
        float v = xr[j];
        d0 = fmaf(v, Wh[j],      d0);
        d1 = fmaf(v, Wh[DM + j], d1);
    }
    #pragma unroll
    for (int o = 16; o > 0; o >>= 1) {
        d0 += __shfl_down_sync(0xffffffffu, d0, o);
        d1 += __shfl_down_sync(0xffffffffu, d1, o);
    }
    if (lane == 0) {
        g_flat_e[2 * gw]     = ((int)floorf(d0 * 8.0f)) & 63;
        g_flat_e[2 * gw + 1] = ((int)floorf(d1 * 8.0f)) & 63;
    }
}

// ---------------- 2) order-preserving rank -----------------------------------
__global__ void rank_kernel() {
    __shared__ int counts[NE];
    __shared__ int whist[32][NE];
    __shared__ int wpref[32][NE];
    __shared__ int ttot[NE];
    int tid  = threadIdx.x;
    int w    = tid >> 5;
    int lane = tid & 31;
    unsigned lmask = (1u << lane) - 1u;

    if (tid < NE) counts[tid] = 0;
    for (int j = tid; j < NE * CAPP; j += 1024) g_slot_tok[j] = -1;
    __syncthreads();

    for (int tile = 0; tile < (T_TOK * 2) / 1024; tile++) {
        for (int j = tid; j < 32 * NE; j += 1024) (&whist[0][0])[j] = 0;
        __syncthreads();

        int i = tile * 1024 + tid;
        int e = g_flat_e[i];
        unsigned m  = __match_any_sync(0xffffffffu, e);
        int prior   = __popc(m & lmask);
        if ((m & lmask) == 0) whist[w][e] = __popc(m);
        __syncthreads();

        if (tid < NE) {
            int s = 0;
            #pragma unroll
            for (int ww = 0; ww < 32; ww++) { wpref[ww][tid] = s; s += whist[ww][tid]; }
            ttot[tid] = s;
        }
        __syncthreads();

        int pos = counts[e] + wpref[w][e] + prior;
        if (pos < CAP) {
            g_entry_slot[i]            = e * CAPP + pos;
            g_slot_tok[e * CAPP + pos] = i >> 1;
        } else {
            g_entry_slot[i] = -1;
        }
        __syncthreads();
        if (tid < NE) counts[tid] += ttot[tid];
        __syncthreads();
    }
}

// Permuted-B addressing:
//  element (k,n) of a 32x128 chunk: ks=k>>3, q=k&3, kb=(k>>2)&1,
//  wn=n>>6, nf=(n>>3)&7, g=n&7, row=q*8+g, w=nf*2+kb, v=w>>2,
//  f = q ^ (wn<<1) ^ (g>>2)   (2-bit xor swizzle; conflict-free R & W)
//  word_addr = ((ks*2+wn)*32 + row)*16 + ((v^f)<<2) + (w&3)

// ---------------- 3) GEMM1: H = gelu(gather(x) @ W1 + b1)  (mma.sync tf32) ---
__global__ __launch_bounds__(256, 2) void xw1_kernel(
        const float* __restrict__ x, const float* __restrict__ W1,
        const float* __restrict__ b1) {
    extern __shared__ char smem[];
    uint32_t sb = smem_u32(smem);
    int tid = threadIdx.x, lane = tid & 31, wid = tid >> 5;
    int wm = wid & 3, wn = wid >> 2;
    int g = lane >> 2, q = lane & 3;
    int n0 = blockIdx.x * 128, mt = blockIdx.y, e = blockIdx.z;

    const float* Wb = W1 + (size_t)e * DM * DFF;

    int tok[4];
    #pragma unroll
    for (int i = 0; i < 4; i++)
        tok[i] = g_slot_tok[e * CAPP + mt * 128 + (tid >> 3) + 32 * i];

    float acc[2][8][4];
    #pragma unroll
    for (int mf = 0; mf < 2; mf++)
        #pragma unroll
        for (int nf = 0; nf < 8; nf++)
            #pragma unroll
            for (int j = 0; j < 4; j++) acc[mf][nf][j] = 0.f;

    float4 regA[4], regB[4];
    int akq = (tid & 7) * 4;

    // B writer: per warp q/kb constant; per-lane j-offsets loop-invariant
    int qw = wid & 3, kbw = (wid >> 2) & 1;
    uint32_t boff[4];
    #pragma unroll
    for (int j = 0; j < 4; j++) {
        int n = lane * 4 + j;
        int wnn = n >> 6, nf = (n >> 3) & 7, gg = n & 7;
        int w = nf * 2 + kbw, vv = w >> 2;
        int ff = qw ^ (wnn << 1) ^ (gg >> 2);
        boff[j] = (uint32_t)(((wnn * 32 + qw * 8 + gg) * 16 + ((vv ^ ff) << 2) + (w & 3)) * 4);
    }

    auto ldg = [&](int k0) {
        #pragma unroll
        for (int i = 0; i < 4; i++) {
            int t = tok[i];
            regA[i] = (t >= 0) ? *(const float4*)(x + (size_t)t * DM + k0 + akq)
                               : make_float4(0.f, 0.f, 0.f, 0.f);
        }
        #pragma unroll
        for (int i = 0; i < 4; i++) {
            int kk = wid + 8 * i;
            regB[i] = *(const float4*)(Wb + (size_t)(k0 + kk) * DFF + n0 + lane * 4);
        }
    };
    auto sts = [&](int st) {
        char* Ab = smem + st * A_BUF;
        char* Bb = smem + 2 * A_BUF + st * BP_BUF;
        #pragma unroll
        for (int i = 0; i < 4; i++)
            *(uint4*)(Ab + ((tid >> 3) + 32 * i) * A_STRIDE + akq * 4) = cvt4(regA[i]);
        #pragma unroll
        for (int i = 0; i < 4; i++) {
            uint4 t = cvt4(regB[i]);
            char* base = Bb + i * 4096;
            *(uint32_t*)(base + boff[0]) = t.x;
            *(uint32_t*)(base + boff[1]) = t.y;
            *(uint32_t*)(base + boff[2]) = t.z;
            *(uint32_t*)(base + boff[3]) = t.w;
        }
    };
    int arow = wm * 32 + (lane & 7) + ((lane >> 3) & 1) * 8;
    int agr  = (lane >> 4);
    int fr = q ^ (wn << 1) ^ (g >> 2);
    uint32_t bthr = (uint32_t)((wn * 32 + q * 8 + g) * 64);
    auto compute = [&](int st) {
        uint32_t Abase = sb + st * A_BUF;
        uint32_t Bbase = sb + 2 * A_BUF + st * BP_BUF + bthr;
        #pragma unroll
        for (int ks = 0; ks < 4; ks++) {
            uint32_t af[2][4];
            ldsm4(af[0], Abase + arow * A_STRIDE + (agr + 2 * ks) * 16);
            ldsm4(af[1], Abase + (arow + 16) * A_STRIDE + (agr + 2 * ks) * 16);
            uint32_t bw[16];
            uint32_t kb2 = Bbase + ks * 4096;
            #pragma unroll
            for (int v = 0; v < 4; v++)
                lds128(&bw[v * 4], kb2 + (uint32_t)(((v ^ fr) & 3) << 4));
            #pragma unroll
            for (int nf = 0; nf < 8; nf++) {
                mma8(acc[0][nf], af[0], &bw[nf * 2]);
                mma8(acc[1][nf], af[1], &bw[nf * 2]);
            }
        }
    };

    ldg(0); sts(0); __syncthreads();
    #pragma unroll 1
    for (int c = 0; c < 16; c++) {
        if (c + 1 < 16) ldg((c + 1) * 32);
        compute(c & 1);
        if (c + 1 < 16) { sts((c + 1) & 1); __syncthreads(); }
    }

    const float* b1e = b1 + (size_t)e * DFF + n0;
    #pragma unroll
    for (int nf = 0; nf < 8; nf++) {
        int col = wn * 64 + nf * 8 + 2 * q;
        float2 bb = *(const float2*)(b1e + col);
        #pragma unroll
        for (int mf = 0; mf < 2; mf++) {
            int r0 = mt * 128 + wm * 32 + mf * 16 + g;
            float* p0 = g_H + ((size_t)e * CAPP + r0) * DFF + n0 + col;
            float2 o0 = make_float2(gelu_f(acc[mf][nf][0] + bb.x),
                                    gelu_f(acc[mf][nf][1] + bb.y));
            *(float2*)p0 = o0;
            float2 o1 = make_float2(gelu_f(acc[mf][nf][2] + bb.x),
                                    gelu_f(acc[mf][nf][3] + bb.y));
            *(float2*)(p0 + 8 * DFF) = o1;
        }
    }
}

// ---------------- 4) GEMM2: Y = H @ W2 + b2  (mma.sync tf32) ------------------
__global__ __launch_bounds__(256, 2) void hw2_kernel(
        const float* __restrict__ W2, const float* __restrict__ b2) {
    extern __shared__ char smem[];
    uint32_t sb = smem_u32(smem);
    int tid = threadIdx.x, lane = tid & 31, wid = tid >> 5;
    int wm = wid & 3, wn = wid >> 2;
    int g = lane >> 2, q = lane & 3;
    int n0 = blockIdx.x * 128, mt = blockIdx.y, e = blockIdx.z;

    const float* Ab0 = g_H + ((size_t)e * CAPP + mt * 128) * DFF;
    const float* Wb  = W2 + (size_t)e * DFF * DM;

    float acc[2][8][4];
    #pragma unroll
    for (int mf = 0; mf < 2; mf++)
        #pragma unroll
        for (int nf = 0; nf < 8; nf++)
            #pragma unroll
            for (int j = 0; j < 4; j++) acc[mf][nf][j] = 0.f;

    float4 regA[4], regB[4];
    int akq = (tid & 7) * 4;

    int qw = wid & 3, kbw = (wid >> 2) & 1;
    uint32_t boff[4];
    #pragma unroll
    for (int j = 0; j < 4; j++) {
        int n = lane * 4 + j;
        int wnn = n >> 6, nf = (n >> 3) & 7, gg = n & 7;
        int w = nf * 2 + kbw, vv = w >> 2;
        int ff = qw ^ (wnn << 1) ^ (gg >> 2);
        boff[j] = (uint32_t)(((wnn * 32 + qw * 8 + gg) * 16 + ((vv ^ ff) << 2) + (w & 3)) * 4);
    }

    auto ldg = [&](int k0) {
        #pragma unroll
        for (int i = 0; i < 4; i++) {
            int m = (tid >> 3) + 32 * i;
            regA[i] = *(const float4*)(Ab0 + (size_t)m * DFF + k0 + akq);
        }
        #pragma unroll
        for (int i = 0; i < 4; i++) {
            int kk = wid + 8 * i;
            regB[i] = *(const float4*)(Wb + (size_t)(k0 + kk) * DM + n0 + lane * 4);
        }
    };
    auto sts = [&](int st) {
        char* Ab = smem + st * A_BUF;
        char* Bb = smem + 2 * A_BUF + st * BP_BUF;
        #pragma unroll
        for (int i = 0; i < 4; i++)
            *(uint4*)(Ab + ((tid >> 3) + 32 * i) * A_STRIDE + akq * 4) = cvt4(regA[i]);
        #pragma unroll
        for (int i = 0; i < 4; i++) {
            uint4 t = cvt4(regB[i]);
            char* base = Bb + i * 4096;
            *(uint32_t*)(base + boff[0]) = t.x;
            *(uint32_t*)(base + boff[1]) = t.y;
            *(uint32_t*)(base + boff[2]) = t.z;
            *(uint32_t*)(base + boff[3]) = t.w;
        }
    };
    int arow = wm * 32 + (lane & 7) + ((lane >> 3) & 1) * 8;
    int agr  = (lane >> 4);
    int fr = q ^ (wn << 1) ^ (g >> 2);
    uint32_t bthr = (uint32_t)((wn * 32 + q * 8 + g) * 64);
    auto compute = [&](int st) {
        uint32_t Abase = sb + st * A_BUF;
        uint32_t Bbase = sb + 2 * A_BUF + st * BP_BUF + bthr;
        #pragma unroll
        for (int ks = 0; ks < 4; ks++) {
            uint32_t af[2][4];
            ldsm4(af[0], Abase + arow * A_STRIDE + (agr + 2 * ks) * 16);
            ldsm4(af[1], Abase + (arow + 16) * A_STRIDE + (agr + 2 * ks) * 16);
            uint32_t bw[16];
            uint32_t kb2 = Bbase + ks * 4096;
            #pragma unroll
            for (int v = 0; v < 4; v++)
                lds128(&bw[v * 4], kb2 + (uint32_t)(((v ^ fr) & 3) << 4));
            #pragma unroll
            for (int nf = 0; nf < 8; nf++) {
                mma8(acc[0][nf], af[0], &bw[nf * 2]);
                mma8(acc[1][nf], af[1], &bw[nf * 2]);
            }
        }
    };

    ldg(0); sts(0); __syncthreads();
    #pragma unroll 1
    for (int c = 0; c < 64; c++) {
        if (c + 1 < 64) ldg((c + 1) * 32);
        compute(c & 1);
        if (c + 1 < 64) { sts((c + 1) & 1); __syncthreads(); }
    }

    const float* b2e = b2 + (size_t)e * DM + n0;
    #pragma unroll
    for (int nf = 0; nf < 8; nf++) {
        int col = wn * 64 + nf * 8 + 2 * q;
        float2 bb = *(const float2*)(b2e + col);
        #pragma unroll
        for (int mf = 0; mf < 2; mf++) {
            int r0 = mt * 128 + wm * 32 + mf * 16 + g;
            float* p0 = g_Y + ((size_t)e * CAPP + r0) * DM + n0 + col;
            float2 o0 = make_float2(acc[mf][nf][0] + bb.x, acc[mf][nf][1] + bb.y);
            *(float2*)p0 = o0;
            float2 o1 = make_float2(acc[mf][nf][2] + bb.x, acc[mf][nf][3] + bb.y);
            *(float2*)(p0 + 8 * DM) = o1;
        }
    }
}

// ---------------- 5) output gather + mean ------------------------------------
__global__ void out_kernel(float* __restrict__ out) {
    int idx = blockIdx.x * blockDim.x + threadIdx.x;
    if (idx >= T_TOK * DM / 4) return;
    int t  = idx / (DM / 4);
    int d4 = (idx % (DM / 4)) * 4;
    int s0 = g_entry_slot[2 * t];
    int s1 = g_entry_slot[2 * t + 1];
    float4 r = make_float4(0.f, 0.f, 0.f, 0.f);
    if (s0 >= 0) {
        float4 v = *(const float4*)(g_Y + (size_t)s0 * DM + d4);
        r.x += v.x; r.y += v.y; r.z += v.z; r.w += v.w;
    }
    if (s1 >= 0) {
        float4 v = *(const float4*)(g_Y + (size_t)s1 * DM + d4);
        r.x += v.x; r.y += v.y; r.z += v.z; r.w += v.w;
    }
    r.x *= 0.5f; r.y *= 0.5f; r.z *= 0.5f; r.w *= 0.5f;
    *(float4*)(out + (size_t)idx * 4) = r;
}

// ---------------- launch -----------------------------------------------------
extern "C" void kernel_launch(void* const* d_in, const int* in_sizes, int n_in,
                              void* d_out, int out_size) {
    const float* x   = (const float*)d_in[0];
    const float* Wh  = (const float*)d_in[1];
    const float* W1  = (const float*)d_in[2];
    const float* b1  = (const float*)d_in[3];
    const float* W2  = (const float*)d_in[4];
    const float* b2  = (const float*)d_in[5];
    float* out = (float*)d_out;

    cudaFuncSetAttribute(xw1_kernel, cudaFuncAttributeMaxDynamicSharedMemorySize, SMEM_TOT);
    cudaFuncSetAttribute(hw2_kernel, cudaFuncAttributeMaxDynamicSharedMemorySize, SMEM_TOT);

    route_kernel<<<T_TOK / 8, 256>>>(x, Wh);
    rank_kernel<<<1, 1024>>>();
    xw1_kernel<<<dim3(DFF / 128, CAPP / 128, NE), 256, SMEM_TOT>>>(x, W1, b1);
    hw2_kernel<<<dim3(DM / 128, CAPP / 128, NE), 256, SMEM_TOT>>>(W2, b2);
    out_kernel<<<(T_TOK * DM / 4 + 255) / 256, 256>>>(out);
}

// round 8
// speedup vs baseline: 4.0249x; 1.1579x over previous
#include <cuda_runtime.h>
#include <math.h>
#include <stdint.h>

#define T_TOK 8192
#define DM    512
#define DFF   2048
#define NE    64
#define CAP   320
#define CAPP  384   // padded capacity (3 x 128)

// ---------------- scratch ----------------------------------------------------
__device__ int   g_flat_e[T_TOK * 2];
__device__ int   g_entry_slot[T_TOK * 2];
__device__ int   g_slot_tok[NE * CAPP];
__device__ float g_xt[(size_t)T_TOK * DM];       // x pre-rounded to tf32
__device__ float g_H[(size_t)NE * CAPP * DFF];   // stored tf32-rounded
__device__ float g_Y[(size_t)NE * CAPP * DM];

// ---------------- helpers ----------------------------------------------------
__device__ __forceinline__ uint32_t smem_u32(const void* p) {
    uint32_t a;
    asm("{ .reg .u64 t; cvta.to.shared.u64 t, %1; cvt.u32.u64 %0, t; }"
        : "=r"(a) : "l"(p));
    return a;
}
__device__ __forceinline__ uint32_t cvt_tf32(float f) {
    uint32_t r; asm("cvt.rna.tf32.f32 %0, %1;" : "=r"(r) : "f"(f)); return r;
}
__device__ __forceinline__ uint4 cvt4(float4 v) {
    uint4 t;
    t.x = cvt_tf32(v.x); t.y = cvt_tf32(v.y);
    t.z = cvt_tf32(v.z); t.w = cvt_tf32(v.w);
    return t;
}
__device__ __forceinline__ void ldsm4(uint32_t* r, uint32_t addr) {
    asm volatile("ldmatrix.sync.aligned.m8n8.x4.shared.b16 {%0,%1,%2,%3}, [%4];"
                 : "=r"(r[0]), "=r"(r[1]), "=r"(r[2]), "=r"(r[3]) : "r"(addr));
}
__device__ __forceinline__ void lds128(uint32_t* r, uint32_t addr) {
    asm volatile("ld.shared.v4.b32 {%0,%1,%2,%3}, [%4];"
                 : "=r"(r[0]), "=r"(r[1]), "=r"(r[2]), "=r"(r[3]) : "r"(addr));
}
__device__ __forceinline__ void cp16(uint32_t dst, const void* src, int srcsize) {
    asm volatile("cp.async.cg.shared.global [%0], [%1], 16, %2;"
                 :: "r"(dst), "l"(src), "r"(srcsize));
}
__device__ __forceinline__ void cp_commit() {
    asm volatile("cp.async.commit_group;" ::: "memory");
}
__device__ __forceinline__ void cp_wait0() {
    asm volatile("cp.async.wait_group 0;" ::: "memory");
}
__device__ __forceinline__ void mma8(float* d, const uint32_t* a, const uint32_t* b) {
    asm volatile("mma.sync.aligned.m16n8k8.row.col.f32.tf32.tf32.f32 "
                 "{%0,%1,%2,%3}, {%4,%5,%6,%7}, {%8,%9}, {%0,%1,%2,%3};"
                 : "+f"(d[0]), "+f"(d[1]), "+f"(d[2]), "+f"(d[3])
                 : "r"(a[0]), "r"(a[1]), "r"(a[2]), "r"(a[3]),
                   "r"(b[0]), "r"(b[1]));
}
__device__ __forceinline__ float gelu_f(float h) {
    return 0.5f * h * (1.0f + erff(h * 0.70710678118654752f));
}
__device__ __forceinline__ float gelu_t(float h) {   // gelu rounded to tf32
    return __uint_as_float(cvt_tf32(gelu_f(h)));
}

// smem geometry (bytes)
#define A_STRIDE 144                       // 32 k-floats + 4 pad (16B-aligned rows)
#define A_BUF    (128 * A_STRIDE)          // 18432
#define BP_BUF   16384                     // permuted B: 4096 words
#define SMEM_TOT (2 * A_BUF + 2 * BP_BUF)  // 69632

// ---------------- 0) pre-round x to tf32 -------------------------------------
__global__ void cvt_x_kernel(const float* __restrict__ x) {
    int idx = blockIdx.x * blockDim.x + threadIdx.x;   // over T*DM/4
    if (idx >= T_TOK * DM / 4) return;
    float4 v = *(const float4*)(x + (size_t)idx * 4);
    uint4 t = cvt4(v);
    *(uint4*)(g_xt + (size_t)idx * 4) = t;
}

// ---------------- 1) routing -------------------------------------------------
__global__ void route_kernel(const float* __restrict__ x,
                             const float* __restrict__ Wh) {
    int gw   = (blockIdx.x * blockDim.x + threadIdx.x) >> 5;
    int lane = threadIdx.x & 31;
    if (gw >= T_TOK) return;
    const float* xr = x + (size_t)gw * DM;
    float d0 = 0.f, d1 = 0.f;
    #pragma unroll
    for (int j = lane; j < DM; j += 32) {
        float v = xr[j];
        d0 = fmaf(v, Wh[j],      d0);
        d1 = fmaf(v, Wh[DM + j], d1);
    }
    #pragma unroll
    for (int o = 16; o > 0; o >>= 1) {
        d0 += __shfl_down_sync(0xffffffffu, d0, o);
        d1 += __shfl_down_sync(0xffffffffu, d1, o);
    }
    if (lane == 0) {
        g_flat_e[2 * gw]     = ((int)floorf(d0 * 8.0f)) & 63;
        g_flat_e[2 * gw + 1] = ((int)floorf(d1 * 8.0f)) & 63;
    }
}

// ---------------- 2) order-preserving rank -----------------------------------
__global__ void rank_kernel() {
    __shared__ int counts[NE];
    __shared__ int whist[32][NE];
    __shared__ int wpref[32][NE];
    __shared__ int ttot[NE];
    int tid  = threadIdx.x;
    int w    = tid >> 5;
    int lane = tid & 31;
    unsigned lmask = (1u << lane) - 1u;

    if (tid < NE) counts[tid] = 0;
    for (int j = tid; j < NE * CAPP; j += 1024) g_slot_tok[j] = -1;
    __syncthreads();

    for (int tile = 0; tile < (T_TOK * 2) / 1024; tile++) {
        for (int j = tid; j < 32 * NE; j += 1024) (&whist[0][0])[j] = 0;
        __syncthreads();

        int i = tile * 1024 + tid;
        int e = g_flat_e[i];
        unsigned m  = __match_any_sync(0xffffffffu, e);
        int prior   = __popc(m & lmask);
        if ((m & lmask) == 0) whist[w][e] = __popc(m);
        __syncthreads();

        if (tid < NE) {
            int s = 0;
            #pragma unroll
            for (int ww = 0; ww < 32; ww++) { wpref[ww][tid] = s; s += whist[ww][tid]; }
            ttot[tid] = s;
        }
        __syncthreads();

        int pos = counts[e] + wpref[w][e] + prior;
        if (pos < CAP) {
            g_entry_slot[i]            = e * CAPP + pos;
            g_slot_tok[e * CAPP + pos] = i >> 1;
        } else {
            g_entry_slot[i] = -1;
        }
        __syncthreads();
        if (tid < NE) counts[tid] += ttot[tid];
        __syncthreads();
    }
}

// Permuted-B addressing (unchanged from R5):
//  f = q ^ (wn<<1) ^ (g>>2); word = ((ks*2+wn)*32 + q*8+g)*16 + ((v^f)<<2) + (w&3)

// ---------------- 3) GEMM1: H = gelu(gather(x_t) @ W1 + b1) ------------------
__global__ __launch_bounds__(256, 2) void xw1_kernel(
        const float* __restrict__ W1, const float* __restrict__ b1) {
    extern __shared__ char smem[];
    uint32_t sb = smem_u32(smem);
    int tid = threadIdx.x, lane = tid & 31, wid = tid >> 5;
    int wm = wid & 3, wn = wid >> 2;
    int g = lane >> 2, q = lane & 3;
    int n0 = blockIdx.x * 128, mt = blockIdx.y, e = blockIdx.z;

    const float* Wb = W1 + (size_t)e * DM * DFF;

    int tok[4];
    #pragma unroll
    for (int i = 0; i < 4; i++)
        tok[i] = g_slot_tok[e * CAPP + mt * 128 + (tid >> 3) + 32 * i];

    float acc[2][8][4];
    #pragma unroll
    for (int mf = 0; mf < 2; mf++)
        #pragma unroll
        for (int nf = 0; nf < 8; nf++)
            #pragma unroll
            for (int j = 0; j < 4; j++) acc[mf][nf][j] = 0.f;

    float4 regB[4];
    int akq = (tid & 7) * 4;

    int qw = wid & 3, kbw = (wid >> 2) & 1;
    uint32_t boff[4];
    #pragma unroll
    for (int j = 0; j < 4; j++) {
        int n = lane * 4 + j;
        int wnn = n >> 6, nf = (n >> 3) & 7, gg = n & 7;
        int w = nf * 2 + kbw, vv = w >> 2;
        int ff = qw ^ (wnn << 1) ^ (gg >> 2);
        boff[j] = (uint32_t)(((wnn * 32 + qw * 8 + gg) * 16 + ((vv ^ ff) << 2) + (w & 3)) * 4);
    }

    auto cpA = [&](int c) {                 // async A: gather tf32 rows of x_t
        int st = c & 1, k0 = c * 32;
        uint32_t dstb = sb + st * A_BUF + (uint32_t)(tid >> 3) * A_STRIDE + (tid & 7) * 16;
        #pragma unroll
        for (int i = 0; i < 4; i++) {
            int t = tok[i];
            const float* src = g_xt + (size_t)(t >= 0 ? t : 0) * DM + k0 + akq;
            cp16(dstb + (uint32_t)(32 * i) * A_STRIDE, src, t >= 0 ? 16 : 0);
        }
    };
    auto ldgB = [&](int k0) {
        #pragma unroll
        for (int i = 0; i < 4; i++) {
            int kk = wid + 8 * i;
            regB[i] = *(const float4*)(Wb + (size_t)(k0 + kk) * DFF + n0 + lane * 4);
        }
    };
    auto stsB = [&](int st) {
        char* Bb = smem + 2 * A_BUF + st * BP_BUF;
        #pragma unroll
        for (int i = 0; i < 4; i++) {
            uint4 t = cvt4(regB[i]);
            char* base = Bb + i * 4096;
            *(uint32_t*)(base + boff[0]) = t.x;
            *(uint32_t*)(base + boff[1]) = t.y;
            *(uint32_t*)(base + boff[2]) = t.z;
            *(uint32_t*)(base + boff[3]) = t.w;
        }
    };
    int arow = wm * 32 + (lane & 7) + ((lane >> 3) & 1) * 8;
    int agr  = (lane >> 4);
    int fr = q ^ (wn << 1) ^ (g >> 2);
    uint32_t bthr = (uint32_t)((wn * 32 + q * 8 + g) * 64);
    auto compute = [&](int st) {
        uint32_t Abase = sb + st * A_BUF;
        uint32_t Bbase = sb + 2 * A_BUF + st * BP_BUF + bthr;
        #pragma unroll
        for (int ks = 0; ks < 4; ks++) {
            uint32_t af[2][4];
            ldsm4(af[0], Abase + arow * A_STRIDE + (agr + 2 * ks) * 16);
            ldsm4(af[1], Abase + (arow + 16) * A_STRIDE + (agr + 2 * ks) * 16);
            uint32_t bw[16];
            uint32_t kb2 = Bbase + ks * 4096;
            #pragma unroll
            for (int v = 0; v < 4; v++)
                lds128(&bw[v * 4], kb2 + (uint32_t)(((v ^ fr) & 3) << 4));
            #pragma unroll
            for (int nf = 0; nf < 8; nf++) {
                mma8(acc[0][nf], af[0], &bw[nf * 2]);
                mma8(acc[1][nf], af[1], &bw[nf * 2]);
            }
        }
    };

    ldgB(0); cpA(0); cp_commit(); stsB(0); cp_wait0(); __syncthreads();
    #pragma unroll 1
    for (int c = 0; c < 16; c++) {
        if (c + 1 < 16) { ldgB((c + 1) * 32); cpA(c + 1); cp_commit(); }
        compute(c & 1);
        if (c + 1 < 16) { stsB((c + 1) & 1); cp_wait0(); __syncthreads(); }
    }

    const float* b1e = b1 + (size_t)e * DFF + n0;
    #pragma unroll
    for (int nf = 0; nf < 8; nf++) {
        int col = wn * 64 + nf * 8 + 2 * q;
        float2 bb = *(const float2*)(b1e + col);
        #pragma unroll
        for (int mf = 0; mf < 2; mf++) {
            int r0 = mt * 128 + wm * 32 + mf * 16 + g;
            float* p0 = g_H + ((size_t)e * CAPP + r0) * DFF + n0 + col;
            float2 o0 = make_float2(gelu_t(acc[mf][nf][0] + bb.x),
                                    gelu_t(acc[mf][nf][1] + bb.y));
            *(float2*)p0 = o0;
            float2 o1 = make_float2(gelu_t(acc[mf][nf][2] + bb.x),
                                    gelu_t(acc[mf][nf][3] + bb.y));
            *(float2*)(p0 + 8 * DFF) = o1;
        }
    }
}

// ---------------- 4) GEMM2: Y = H @ W2 + b2 ----------------------------------
__global__ __launch_bounds__(256, 2) void hw2_kernel(
        const float* __restrict__ W2, const float* __restrict__ b2) {
    extern __shared__ char smem[];
    uint32_t sb = smem_u32(smem);
    int tid = threadIdx.x, lane = tid & 31, wid = tid >> 5;
    int wm = wid & 3, wn = wid >> 2;
    int g = lane >> 2, q = lane & 3;
    int n0 = blockIdx.x * 128, mt = blockIdx.y, e = blockIdx.z;

    const float* Ab0 = g_H + ((size_t)e * CAPP + mt * 128) * DFF;
    const float* Wb  = W2 + (size_t)e * DFF * DM;

    float acc[2][8][4];
    #pragma unroll
    for (int mf = 0; mf < 2; mf++)
        #pragma unroll
        for (int nf = 0; nf < 8; nf++)
            #pragma unroll
            for (int j = 0; j < 4; j++) acc[mf][nf][j] = 0.f;

    float4 regB[4];
    int akq = (tid & 7) * 4;

    int qw = wid & 3, kbw = (wid >> 2) & 1;
    uint32_t boff[4];
    #pragma unroll
    for (int j = 0; j < 4; j++) {
        int n = lane * 4 + j;
        int wnn = n >> 6, nf = (n >> 3) & 7, gg = n & 7;
        int w = nf * 2 + kbw, vv = w >> 2;
        int ff = qw ^ (wnn << 1) ^ (gg >> 2);
        boff[j] = (uint32_t)(((wnn * 32 + qw * 8 + gg) * 16 + ((vv ^ ff) << 2) + (w & 3)) * 4);
    }

    auto cpA = [&](int c) {                 // async A: H already tf32
        int st = c & 1, k0 = c * 32;
        uint32_t dstb = sb + st * A_BUF + (uint32_t)(tid >> 3) * A_STRIDE + (tid & 7) * 16;
        const float* srcb = Ab0 + (size_t)(tid >> 3) * DFF + k0 + akq;
        #pragma unroll
        for (int i = 0; i < 4; i++)
            cp16(dstb + (uint32_t)(32 * i) * A_STRIDE, srcb + (size_t)(32 * i) * DFF, 16);
    };
    auto ldgB = [&](int k0) {
        #pragma unroll
        for (int i = 0; i < 4; i++) {
            int kk = wid + 8 * i;
            regB[i] = *(const float4*)(Wb + (size_t)(k0 + kk) * DM + n0 + lane * 4);
        }
    };
    auto stsB = [&](int st) {
        char* Bb = smem + 2 * A_BUF + st * BP_BUF;
        #pragma unroll
        for (int i = 0; i < 4; i++) {
            uint4 t = cvt4(regB[i]);
            char* base = Bb + i * 4096;
            *(uint32_t*)(base + boff[0]) = t.x;
            *(uint32_t*)(base + boff[1]) = t.y;
            *(uint32_t*)(base + boff[2]) = t.z;
            *(uint32_t*)(base + boff[3]) = t.w;
        }
    };
    int arow = wm * 32 + (lane & 7) + ((lane >> 3) & 1) * 8;
    int agr  = (lane >> 4);
    int fr = q ^ (wn << 1) ^ (g >> 2);
    uint32_t bthr = (uint32_t)((wn * 32 + q * 8 + g) * 64);
    auto compute = [&](int st) {
        uint32_t Abase = sb + st * A_BUF;
        uint32_t Bbase = sb + 2 * A_BUF + st * BP_BUF + bthr;
        #pragma unroll
        for (int ks = 0; ks < 4; ks++) {
            uint32_t af[2][4];
            ldsm4(af[0], Abase + arow * A_STRIDE + (agr + 2 * ks) * 16);
            ldsm4(af[1], Abase + (arow + 16) * A_STRIDE + (agr + 2 * ks) * 16);
            uint32_t bw[16];
            uint32_t kb2 = Bbase + ks * 4096;
            #pragma unroll
            for (int v = 0; v < 4; v++)
                lds128(&bw[v * 4], kb2 + (uint32_t)(((v ^ fr) & 3) << 4));
            #pragma unroll
            for (int nf = 0; nf < 8; nf++) {
                mma8(acc[0][nf], af[0], &bw[nf * 2]);
                mma8(acc[1][nf], af[1], &bw[nf * 2]);
            }
        }
    };

    ldgB(0); cpA(0); cp_commit(); stsB(0); cp_wait0(); __syncthreads();
    #pragma unroll 1
    for (int c = 0; c < 64; c++) {
        if (c + 1 < 64) { ldgB((c + 1) * 32); cpA(c + 1); cp_commit(); }
        compute(c & 1);
        if (c + 1 < 64) { stsB((c + 1) & 1); cp_wait0(); __syncthreads(); }
    }

    const float* b2e = b2 + (size_t)e * DM + n0;
    #pragma unroll
    for (int nf = 0; nf < 8; nf++) {
        int col = wn * 64 + nf * 8 + 2 * q;
        float2 bb = *(const float2*)(b2e + col);
        #pragma unroll
        for (int mf = 0; mf < 2; mf++) {
            int r0 = mt * 128 + wm * 32 + mf * 16 + g;
            float* p0 = g_Y + ((size_t)e * CAPP + r0) * DM + n0 + col;
            float2 o0 = make_float2(acc[mf][nf][0] + bb.x, acc[mf][nf][1] + bb.y);
            *(float2*)p0 = o0;
            float2 o1 = make_float2(acc[mf][nf][2] + bb.x, acc[mf][nf][3] + bb.y);
            *(float2*)(p0 + 8 * DM) = o1;
        }
    }
}

// ---------------- 5) output gather + mean ------------------------------------
__global__ void out_kernel(float* __restrict__ out) {
    int idx = blockIdx.x * blockDim.x + threadIdx.x;
    if (idx >= T_TOK * DM / 4) return;
    int t  = idx / (DM / 4);
    int d4 = (idx % (DM / 4)) * 4;
    int s0 = g_entry_slot[2 * t];
    int s1 = g_entry_slot[2 * t + 1];
    float4 r = make_float4(0.f, 0.f, 0.f, 0.f);
    if (s0 >= 0) {
        float4 v = *(const float4*)(g_Y + (size_t)s0 * DM + d4);
        r.x += v.x; r.y += v.y; r.z += v.z; r.w += v.w;
    }
    if (s1 >= 0) {
        float4 v = *(const float4*)(g_Y + (size_t)s1 * DM + d4);
        r.x += v.x; r.y += v.y; r.z += v.z; r.w += v.w;
    }
    r.x *= 0.5f; r.y *= 0.5f; r.z *= 0.5f; r.w *= 0.5f;
    *(float4*)(out + (size_t)idx * 4) = r;
}

// ---------------- launch -----------------------------------------------------
extern "C" void kernel_launch(void* const* d_in, const int* in_sizes, int n_in,
                              void* d_out, int out_size) {
    const float* x   = (const float*)d_in[0];
    const float* Wh  = (const float*)d_in[1];
    const float* W1  = (const float*)d_in[2];
    const float* b1  = (const float*)d_in[3];
    const float* W2  = (const float*)d_in[4];
    const float* b2  = (const float*)d_in[5];
    float* out = (float*)d_out;

    cudaFuncSetAttribute(xw1_kernel, cudaFuncAttributeMaxDynamicSharedMemorySize, SMEM_TOT);
    cudaFuncSetAttribute(hw2_kernel, cudaFuncAttributeMaxDynamicSharedMemorySize, SMEM_TOT);

    route_kernel<<<T_TOK / 8, 256>>>(x, Wh);
    cvt_x_kernel<<<(T_TOK * DM / 4 + 255) / 256, 256>>>(x);
    rank_kernel<<<1, 1024>>>();
    xw1_kernel<<<dim3(DFF / 128, CAPP / 128, NE), 256, SMEM_TOT>>>(W1, b1);
    hw2_kernel<<<dim3(DM / 128, CAPP / 128, NE), 256, SMEM_TOT>>>(W2, b2);
    out_kernel<<<(T_TOK * DM / 4 + 255) / 256, 256>>>(out);
}